// round 1
// baseline (speedup 1.0000x reference)
#include <cuda_runtime.h>
#include <math.h>

// Problem constants (fixed by dataset)
#define MAXN 100000
#define MAXE 3200000
#define FIN  128
#define HID  64

// ---------------- static device scratch (no dynamic allocation) -------------
__device__ int   d_deg[MAXN];
__device__ float d_dinv[MAXN];
__device__ int   d_needed[MAXN];     // node is in V1 (needs layer-1 output)
__device__ int   d_isout[MAXN];      // node is an output node (last of its graph)
__device__ int   d_slot[MAXN];       // node -> compact slot (-1 = none)
__device__ int   d_slotnode[MAXN];   // slot -> node
__device__ __align__(16) float d_xagg[(size_t)MAXN * FIN]; // per-slot 128-f32 accumulator
__device__ float d_tval[MAXN];       // per-slot scalar t = relu(h1)@W2
__device__ int2  d_l2[MAXE];         // compacted edges whose dst is an output node
__device__ int   d_outnodes[MAXN];
__device__ int   d_nslots;
__device__ int   d_nl2;
__device__ int   d_nout;

// vectorized fp32 reduction (sm_90+)
__device__ __forceinline__ void red_add_v4(float* addr, float a, float b, float c, float d) {
    asm volatile("red.global.add.v4.f32 [%0], {%1,%2,%3,%4};"
                 :: "l"(addr), "f"(a), "f"(b), "f"(c), "f"(d) : "memory");
}

// ---------------------------------------------------------------------------
__global__ void k_init(int N) {
    int i = blockIdx.x * blockDim.x + threadIdx.x;
    if (i < N) {
        d_deg[i]    = 0;
        d_needed[i] = 0;
        d_isout[i]  = 0;
        d_slot[i]   = -1;
    }
    if (i == 0) { d_nslots = 0; d_nl2 = 0; d_nout = 0; }
}

// in-degree histogram (self-loop added later via +1)
__global__ void k_deg(const int* __restrict__ dst, int E) {
    int i = blockIdx.x * blockDim.x + threadIdx.x;
    if (i < E) atomicAdd(&d_deg[dst[i]], 1);
}

// dinv + find output nodes (last node of each graph in sorted batch)
__global__ void k_mark(const int* __restrict__ batch, int N) {
    int i = blockIdx.x * blockDim.x + threadIdx.x;
    if (i >= N) return;
    d_dinv[i] = rsqrtf((float)(d_deg[i] + 1));
    bool last = (i == N - 1) || (batch[i] != batch[i + 1]);
    if (last) {
        d_isout[i]  = 1;
        d_needed[i] = 1;
        int o = atomicAdd(&d_nout, 1);
        d_outnodes[o] = i;
    }
}

// collect layer-2 edges (dst is an output node); mark their sources as needed
__global__ void k_l2collect(const int* __restrict__ src, const int* __restrict__ dst, int E) {
    int i = blockIdx.x * blockDim.x + threadIdx.x;
    if (i >= E) return;
    int d = dst[i];
    if (d_isout[d]) {
        int s = src[i];
        d_needed[s] = 1;
        int p = atomicAdd(&d_nl2, 1);
        d_l2[p] = make_int2(s, d);
    }
}

// assign compact slots to needed nodes; zero their xagg rows
__global__ void k_slots(int N) {
    int i = blockIdx.x * blockDim.x + threadIdx.x;
    if (i >= N) return;
    if (d_needed[i]) {
        int s = atomicAdd(&d_nslots, 1);
        d_slot[i] = s;
        d_slotnode[s] = i;
        float4* row = (float4*)&d_xagg[(size_t)s * FIN];
        #pragma unroll
        for (int k = 0; k < FIN / 4; k++) row[k] = make_float4(0.f, 0.f, 0.f, 0.f);
    }
}

// scan all edges; for edges into V1 nodes, scatter x[src]*dinv[src] (128 floats)
// into xagg[slot[dst]]. Warp-cooperative per matched edge.
__global__ void k_gather(const int* __restrict__ src, const int* __restrict__ dst,
                         const float4* __restrict__ x4, int E) {
    int idx  = blockIdx.x * blockDim.x + threadIdx.x;
    int lane = threadIdx.x & 31;
    int s = 0, d = 0, pred = 0;
    if (idx < E) {
        d = dst[idx];
        pred = d_needed[d];
        if (pred) s = src[idx];
    }
    unsigned mask = __ballot_sync(0xffffffffu, pred);
    while (mask) {
        int b = __ffs(mask) - 1;
        mask &= mask - 1;
        int bs = __shfl_sync(0xffffffffu, s, b);
        int bd = __shfl_sync(0xffffffffu, d, b);
        int sl  = d_slot[bd];   // uniform per warp -> broadcast load
        float w = d_dinv[bs];
        float4 xv = x4[(size_t)bs * (FIN / 4) + lane];
        red_add_v4(&d_xagg[(size_t)sl * FIN + lane * 4],
                   xv.x * w, xv.y * w, xv.z * w, xv.w * w);
    }
}

// per V1 node: y = xagg*dinv + x*dinv^2 ; h1 = relu(y@W1 + b1) ; t = h1@W2
__global__ void k_compute(const float* __restrict__ x,
                          const float* __restrict__ W1,
                          const float* __restrict__ b1,
                          const float* __restrict__ W2) {
    __shared__ float ysh[FIN];
    __shared__ float redsh[HID];
    int ns = d_nslots;
    int t  = threadIdx.x;   // 0..63
    for (int s = blockIdx.x; s < ns; s += gridDim.x) {
        int v = d_slotnode[s];
        float dv  = d_dinv[v];
        float dv2 = dv * dv;
        #pragma unroll
        for (int k = t; k < FIN; k += HID)
            ysh[k] = d_xagg[(size_t)s * FIN + k] * dv + x[(size_t)v * FIN + k] * dv2;
        __syncthreads();
        float acc = 0.f;
        #pragma unroll 16
        for (int k = 0; k < FIN; k++)
            acc = fmaf(ysh[k], W1[k * HID + t], acc);
        float h = fmaxf(acc + b1[t], 0.f);
        redsh[t] = h * W2[t];
        __syncthreads();
        if (t < 32) {
            float p = redsh[t] + redsh[t + 32];
            #pragma unroll
            for (int o = 16; o > 0; o >>= 1)
                p += __shfl_down_sync(0xffffffffu, p, o);
            if (t == 0) d_tval[s] = p;
        }
        __syncthreads();
    }
}

__global__ void k_initout(float* __restrict__ out, const float* __restrict__ b2, int G) {
    int g = blockIdx.x * blockDim.x + threadIdx.x;
    if (g < G) out[g] = b2[0];
}

// layer-2 edge aggregation into the G outputs
__global__ void k_l2agg(const int* __restrict__ batch, float* __restrict__ out) {
    int n = d_nl2;
    for (int i = blockIdx.x * blockDim.x + threadIdx.x; i < n; i += gridDim.x * blockDim.x) {
        int2 e = d_l2[i];
        float val = d_tval[d_slot[e.x]] * d_dinv[e.x] * d_dinv[e.y];
        atomicAdd(&out[batch[e.y]], val);
    }
}

// layer-2 self-loop term for each output node
__global__ void k_selfloop(const int* __restrict__ batch, float* __restrict__ out) {
    int n = d_nout;
    for (int i = blockIdx.x * blockDim.x + threadIdx.x; i < n; i += gridDim.x * blockDim.x) {
        int v = d_outnodes[i];
        float dv = d_dinv[v];
        atomicAdd(&out[batch[v]], d_tval[d_slot[v]] * dv * dv);
    }
}

// ---------------------------------------------------------------------------
extern "C" void kernel_launch(void* const* d_in, const int* in_sizes, int n_in,
                              void* d_out, int out_size) {
    const float* x    = (const float*)d_in[0];
    const int*   ei   = (const int*)  d_in[1];
    const int*   batch= (const int*)  d_in[2];
    const float* W1   = (const float*)d_in[3];
    const float* b1   = (const float*)d_in[4];
    const float* W2   = (const float*)d_in[5];
    const float* b2   = (const float*)d_in[6];
    float* out = (float*)d_out;

    const int N = in_sizes[2];
    const int E = in_sizes[1] / 2;
    const int G = out_size;

    const int* src = ei;
    const int* dst = ei + E;

    int gN = (N + 255) / 256;
    int gE = (E + 255) / 256;

    k_init      <<<gN, 256>>>(N);
    k_deg       <<<gE, 256>>>(dst, E);
    k_mark      <<<gN, 256>>>(batch, N);
    k_l2collect <<<gE, 256>>>(src, dst, E);
    k_slots     <<<gN, 256>>>(N);
    k_gather    <<<gE, 256>>>(src, dst, (const float4*)x, E);
    k_compute   <<<2048, HID>>>(x, W1, b1, W2);
    k_initout   <<<(G + 63) / 64, 64>>>(out, b2, G);
    k_l2agg     <<<512, 256>>>(batch, out);
    k_selfloop  <<<64, 256>>>(batch, out);
}

// round 3
// speedup vs baseline: 1.3088x; 1.3088x over previous
#include <cuda_runtime.h>
#include <stdint.h>
#include <math.h>

// Problem constants (fixed by dataset)
#define MAXN 100000
#define MAXE 3200000
#define FIN  128
#define HID  64
#define NBW  ((MAXN + 31) / 32)   // bitmap words

// ---------------- static device scratch (no dynamic allocation) -------------
__device__ int      d_deg[MAXN];
__device__ float    d_dinv[MAXN];
__device__ unsigned d_isout_bits[NBW];   // 12.5 KB: L1-resident on every SM
__device__ unsigned d_need_bits[NBW];    // 12.5 KB: L1-resident on every SM
__device__ int      d_slot[MAXN];        // node -> compact slot (valid iff needed)
__device__ int      d_slotnode[MAXN];    // slot -> node
__device__ __align__(16) float d_xagg[(size_t)MAXN * FIN];
__device__ float    d_tval[MAXN];        // per-slot scalar t = relu(h1)@W2
__device__ int2     d_l2[MAXE];          // edges whose dst is an output node
__device__ int      d_outnodes[MAXN];
__device__ int      d_nslots;
__device__ int      d_nl2;
__device__ int      d_nout;

__device__ __forceinline__ void red_add_v4(float* addr, float a, float b, float c, float d) {
    asm volatile("red.global.add.v4.f32 [%0], {%1,%2,%3,%4};"
                 :: "l"(addr), "f"(a), "f"(b), "f"(c), "f"(d) : "memory");
}

__device__ __forceinline__ int test_bit(const unsigned* bits, int i) {
    return (bits[i >> 5] >> (i & 31)) & 1u;
}

// ---------------------------------------------------------------------------
__global__ void k_init(int N) {
    int i = blockIdx.x * blockDim.x + threadIdx.x;
    if (i < N) d_deg[i] = 0;
    if (i < NBW) { d_isout_bits[i] = 0u; d_need_bits[i] = 0u; }
    if (i == 0) { d_nslots = 0; d_nl2 = 0; d_nout = 0; }
}

// output nodes (last of each graph in sorted batch); also init out[] with bias
__global__ void k_mark(const int* __restrict__ batch, int N,
                       float* __restrict__ out, const float* __restrict__ b2, int G) {
    int i = blockIdx.x * blockDim.x + threadIdx.x;
    if (i < G) out[i] = b2[0];
    if (i >= N) return;
    bool last = (i == N - 1) || (batch[i] != batch[i + 1]);
    if (last) {
        atomicOr(&d_isout_bits[i >> 5], 1u << (i & 31));
        atomicOr(&d_need_bits[i >> 5], 1u << (i & 31));
        int o = atomicAdd(&d_nout, 1);
        d_outnodes[o] = i;
    }
}

__device__ __forceinline__ void pass1_one(int sj, int dj) {
    atomicAdd(&d_deg[dj], 1);
    if (test_bit(d_isout_bits, dj)) {
        atomicOr(&d_need_bits[sj >> 5], 1u << (sj & 31));
        int p = atomicAdd(&d_nl2, 1);
        d_l2[p] = make_int2(sj, dj);
    }
}

// fused: in-degree histogram + layer-2 edge collection, 4 edges/thread
__global__ void k_pass1_v4(const int4* __restrict__ src4, const int4* __restrict__ dst4, int E4) {
    int i = blockIdx.x * blockDim.x + threadIdx.x;
    if (i >= E4) return;
    int4 s = __ldg(&src4[i]);
    int4 d = __ldg(&dst4[i]);
    pass1_one(s.x, d.x);
    pass1_one(s.y, d.y);
    pass1_one(s.z, d.z);
    pass1_one(s.w, d.w);
}
// scalar fallback
__global__ void k_pass1_s(const int* __restrict__ src, const int* __restrict__ dst,
                          int start, int E) {
    int i = start + blockIdx.x * blockDim.x + threadIdx.x;
    if (i >= E) return;
    pass1_one(__ldg(&src[i]), __ldg(&dst[i]));
}

// dinv for all nodes; slot + xagg zero for needed nodes
__global__ void k_slots(int N) {
    int i = blockIdx.x * blockDim.x + threadIdx.x;
    if (i >= N) return;
    d_dinv[i] = rsqrtf((float)(d_deg[i] + 1));
    if (test_bit(d_need_bits, i)) {
        int s = atomicAdd(&d_nslots, 1);
        d_slot[i] = s;
        d_slotnode[s] = i;
        float4* row = (float4*)&d_xagg[(size_t)s * FIN];
        #pragma unroll
        for (int k = 0; k < FIN / 4; k++) row[k] = make_float4(0.f, 0.f, 0.f, 0.f);
    }
}

// scan all edges; for edges into needed nodes, scatter x[src]*dinv[src]
__global__ void k_gather(const int* __restrict__ src, const int* __restrict__ dst,
                         const float4* __restrict__ x4, int E) {
    int idx  = blockIdx.x * blockDim.x + threadIdx.x;
    int lane = threadIdx.x & 31;
    int s = 0, d = 0, pred = 0;
    if (idx < E) {
        d = __ldg(&dst[idx]);
        pred = test_bit(d_need_bits, d);        // 12.5 KB bitmap: L1 hit
        if (pred) s = __ldg(&src[idx]);
    }
    unsigned mask = __ballot_sync(0xffffffffu, pred);
    while (mask) {
        int b = __ffs(mask) - 1;
        mask &= mask - 1;
        int bs = __shfl_sync(0xffffffffu, s, b);
        int bd = __shfl_sync(0xffffffffu, d, b);
        int sl = d_slot[bd];
        float w = d_dinv[bs];
        float4 xv = __ldg(&x4[(size_t)bs * (FIN / 4) + lane]);
        red_add_v4(&d_xagg[(size_t)sl * FIN + lane * 4],
                   xv.x * w, xv.y * w, xv.z * w, xv.w * w);
    }
}

// per needed node: y = xagg*dinv + x*dinv^2 ; h1 = relu(y@W1+b1) ; t = h1@W2
__global__ void k_compute(const float* __restrict__ x,
                          const float* __restrict__ W1,
                          const float* __restrict__ b1,
                          const float* __restrict__ W2) {
    __shared__ float ysh[FIN];
    __shared__ float redsh[HID];
    int ns = d_nslots;
    int t  = threadIdx.x;   // 0..63
    for (int s = blockIdx.x; s < ns; s += gridDim.x) {
        int v = d_slotnode[s];
        float dv  = d_dinv[v];
        float dv2 = dv * dv;
        #pragma unroll
        for (int k = t; k < FIN; k += HID)
            ysh[k] = d_xagg[(size_t)s * FIN + k] * dv + x[(size_t)v * FIN + k] * dv2;
        __syncthreads();
        float acc = 0.f;
        #pragma unroll 16
        for (int k = 0; k < FIN; k++)
            acc = fmaf(ysh[k], W1[k * HID + t], acc);
        float h = fmaxf(acc + b1[t], 0.f);
        redsh[t] = h * W2[t];
        __syncthreads();
        if (t < 32) {
            float p = redsh[t] + redsh[t + 32];
            #pragma unroll
            for (int o = 16; o > 0; o >>= 1)
                p += __shfl_down_sync(0xffffffffu, p, o);
            if (t == 0) d_tval[s] = p;
        }
        __syncthreads();
    }
}

// layer-2 edge aggregation + self-loop terms into the G outputs
__global__ void k_final(const int* __restrict__ batch, float* __restrict__ out) {
    int n1 = d_nl2, n2 = d_nout;
    int stride = gridDim.x * blockDim.x;
    for (int i = blockIdx.x * blockDim.x + threadIdx.x; i < n1; i += stride) {
        int2 e = d_l2[i];
        float val = d_tval[d_slot[e.x]] * d_dinv[e.x] * d_dinv[e.y];
        atomicAdd(&out[batch[e.y]], val);
    }
    for (int i = blockIdx.x * blockDim.x + threadIdx.x; i < n2; i += stride) {
        int v = d_outnodes[i];
        float dv = d_dinv[v];
        atomicAdd(&out[batch[v]], d_tval[d_slot[v]] * dv * dv);
    }
}

// ---------------------------------------------------------------------------
extern "C" void kernel_launch(void* const* d_in, const int* in_sizes, int n_in,
                              void* d_out, int out_size) {
    const float* x     = (const float*)d_in[0];
    const int*   ei    = (const int*)  d_in[1];
    const int*   batch = (const int*)  d_in[2];
    const float* W1    = (const float*)d_in[3];
    const float* b1    = (const float*)d_in[4];
    const float* W2    = (const float*)d_in[5];
    const float* b2    = (const float*)d_in[6];
    float* out = (float*)d_out;

    const int N = in_sizes[2];
    const int E = in_sizes[1] / 2;
    const int G = out_size;

    const int* src = ei;
    const int* dst = ei + E;

    int gN = (N + 255) / 256;

    k_init <<<gN, 256>>>(N);
    k_mark <<<gN, 256>>>(batch, N, out, b2, G);

    bool vec_ok = ((E & 3) == 0) &&
                  ((((uintptr_t)src) & 15) == 0) && ((((uintptr_t)dst) & 15) == 0);
    if (vec_ok) {
        int E4 = E / 4;
        k_pass1_v4<<<(E4 + 255) / 256, 256>>>((const int4*)src, (const int4*)dst, E4);
    } else {
        k_pass1_s <<<(E + 255) / 256, 256>>>(src, dst, 0, E);
    }

    k_slots   <<<gN, 256>>>(N);
    k_gather  <<<(E + 255) / 256, 256>>>(src, dst, (const float4*)x, E);
    k_compute <<<2048, HID>>>(x, W1, b1, W2);
    k_final   <<<64, 256>>>(batch, out);
}